// round 9
// baseline (speedup 1.0000x reference)
#include <cuda_runtime.h>
#include <cuda_bf16.h>
#include <cstdint>

#define BB 64
#define II 128
#define AA 16
#define HH 1024
#define BH (BB*HH)
#define ROWS_PER_BLK 4
#define BLKS_PER_BATCH (HH / ROWS_PER_BLK)   // 256

// scratch (static __device__ — no allocations)
__device__ float g_so[BH];              // sign_j * output[b,j]
__device__ float g_ff[BH];              // b_h + relu(x)@|W_x|^T + relu(aux)@|W_aux|^T
__device__ unsigned int g_gq[HH*HH];    // packed bf16: lo = 0.02*|W_h|, hi = |kappa|
__device__ unsigned int g_cnt[BB];      // per-batch arrival counters

// ---------------- prep: pack (0.02*|W_h|, |kappa|) as bf16x2; reset counters ----------------
__global__ void prep_gq(const float4* __restrict__ Wh, const float4* __restrict__ kap) {
    int idx = blockIdx.x * blockDim.x + threadIdx.x;    // over HH*HH/4
    if (idx < BB) g_cnt[idx] = 0u;                      // reset barrier state every call
    if (idx >= HH * HH / 4) return;
    float4 wv = Wh[idx];
    float4 kv = kap[idx];
    uint4 o;
    o.x = (unsigned)__bfloat16_as_ushort(__float2bfloat16_rn(0.02f * fabsf(wv.x)))
        | ((unsigned)__bfloat16_as_ushort(__float2bfloat16_rn(fabsf(kv.x))) << 16);
    o.y = (unsigned)__bfloat16_as_ushort(__float2bfloat16_rn(0.02f * fabsf(wv.y)))
        | ((unsigned)__bfloat16_as_ushort(__float2bfloat16_rn(fabsf(kv.y))) << 16);
    o.z = (unsigned)__bfloat16_as_ushort(__float2bfloat16_rn(0.02f * fabsf(wv.z)))
        | ((unsigned)__bfloat16_as_ushort(__float2bfloat16_rn(fabsf(kv.z))) << 16);
    o.w = (unsigned)__bfloat16_as_ushort(__float2bfloat16_rn(0.02f * fabsf(wv.w)))
        | ((unsigned)__bfloat16_as_ushort(__float2bfloat16_rn(fabsf(kv.w))) << 16);
    ((uint4*)g_gq)[idx] = o;
}

// ---------------- prep: signed output + feedforward drive (warp per output) ----------------
__global__ __launch_bounds__(256) void prep_soff(const float* __restrict__ x,
                                                 const float* __restrict__ outp,
                                                 const float* __restrict__ aux,
                                                 const float* __restrict__ Wx,
                                                 const float* __restrict__ Waux,
                                                 const float* __restrict__ bh,
                                                 const float* __restrict__ mask) {
    const int warp = threadIdx.x >> 5;
    const int lane = threadIdx.x & 31;
    const int row = blockIdx.x * 8 + warp;        // (b,i)
    const int b = row >> 10;
    const int i = row & (HH - 1);

    float4 w = ((const float4*)(Wx + i * II))[lane];
    float4 xv = ((const float4*)(x + b * II))[lane];
    float acc = fmaxf(xv.x, 0.f) * fabsf(w.x) + fmaxf(xv.y, 0.f) * fabsf(w.y)
              + fmaxf(xv.z, 0.f) * fabsf(w.z) + fmaxf(xv.w, 0.f) * fabsf(w.w);
    if (lane < 4) {
        float4 wa = ((const float4*)(Waux + i * AA))[lane];
        float4 av = ((const float4*)(aux + b * AA))[lane];
        acc += fmaxf(av.x, 0.f) * fabsf(wa.x) + fmaxf(av.y, 0.f) * fabsf(wa.y)
             + fmaxf(av.z, 0.f) * fabsf(wa.z) + fmaxf(av.w, 0.f) * fabsf(wa.w);
    }
#pragma unroll
    for (int off = 16; off; off >>= 1) acc += __shfl_down_sync(0xffffffffu, acc, off);
    if (lane == 0) {
        g_ff[row] = acc + bh[i];
        // mask_h[r, j] = sign_j for any r != j (zero diagonal) -> read row (i+1)%H
        float sgn = mask[((i + 1) & (HH - 1)) * HH + i];
        g_so[row] = sgn * outp[row];
    }
}

// ---------------- pass-2 math on one float4 column chunk ----------------
__device__ __forceinline__ float4 plast4(float4 w, uint4 gq, float4 no, float coef) {
    float4 r;
    {
        float g = __bfloat162float(__ushort_as_bfloat16((unsigned short)(gq.x & 0xffff)));
        float q = __bfloat162float(__ushort_as_bfloat16((unsigned short)(gq.x >> 16)));
        r.x = fminf(fmaxf(g + 0.98f * w.x + coef * q * no.x, 0.f), 1.f);
    }
    {
        float g = __bfloat162float(__ushort_as_bfloat16((unsigned short)(gq.y & 0xffff)));
        float q = __bfloat162float(__ushort_as_bfloat16((unsigned short)(gq.y >> 16)));
        r.y = fminf(fmaxf(g + 0.98f * w.y + coef * q * no.y, 0.f), 1.f);
    }
    {
        float g = __bfloat162float(__ushort_as_bfloat16((unsigned short)(gq.z & 0xffff)));
        float q = __bfloat162float(__ushort_as_bfloat16((unsigned short)(gq.z >> 16)));
        r.z = fminf(fmaxf(g + 0.98f * w.z + coef * q * no.z, 0.f), 1.f);
    }
    {
        float g = __bfloat162float(__ushort_as_bfloat16((unsigned short)(gq.w & 0xffff)));
        float q = __bfloat162float(__ushort_as_bfloat16((unsigned short)(gq.w >> 16)));
        r.w = fminf(fmaxf(g + 0.98f * w.w + coef * q * no.w, 0.f), 1.f);
    }
    return r;
}

// ---------------- fused: matvec -> per-batch barrier -> plasticity (wh in regs once) ----------------
__global__ __launch_bounds__(256) void k_fused(const float* __restrict__ wh,
                                               const float* __restrict__ state,
                                               const float* __restrict__ da,
                                               float* __restrict__ out_state,
                                               float* __restrict__ out_output,
                                               float* __restrict__ out_w) {
    __shared__ float red[8 * ROWS_PER_BLK];
    __shared__ float no_sh[ROWS_PER_BLK];
    const int row0 = blockIdx.x * ROWS_PER_BLK;   // 4 consecutive rows, same batch
    const int b = row0 >> 10;
    const int i0 = row0 & (HH - 1);
    const int t = threadIdx.x;                    // 256 threads x 4 cols

    // ---- pass 1: front-batched loads of 4 wh rows (retained in registers) ----
    const float4* wp = (const float4*)(wh + (size_t)row0 * HH) + t;
    float4 w0 = wp[0];
    float4 w1 = wp[256];
    float4 w2 = wp[512];
    float4 w3 = wp[768];
    float4 s  = *(const float4*)(g_so + (b << 10) + 4 * t);

    float a0 = w0.x * s.x + w0.y * s.y + w0.z * s.z + w0.w * s.w;
    float a1 = w1.x * s.x + w1.y * s.y + w1.z * s.z + w1.w * s.w;
    float a2 = w2.x * s.x + w2.y * s.y + w2.z * s.z + w2.w * s.w;
    float a3 = w3.x * s.x + w3.y * s.y + w3.z * s.z + w3.w * s.w;

    // zero-diagonal fixups
#pragma unroll
    for (int r = 0; r < ROWS_PER_BLK; r++) {
        int i = i0 + r;
        if (t == (i >> 2)) {
            int c = i & 3;
            float4 w = (r == 0) ? w0 : (r == 1) ? w1 : (r == 2) ? w2 : w3;
            float wv = (c == 0) ? w.x : (c == 1) ? w.y : (c == 2) ? w.z : w.w;
            float sv = (c == 0) ? s.x : (c == 1) ? s.y : (c == 2) ? s.z : s.w;
            float d = wv * sv;
            if (r == 0) a0 -= d; else if (r == 1) a1 -= d; else if (r == 2) a2 -= d; else a3 -= d;
        }
    }
#pragma unroll
    for (int off = 16; off; off >>= 1) {
        a0 += __shfl_down_sync(0xffffffffu, a0, off);
        a1 += __shfl_down_sync(0xffffffffu, a1, off);
        a2 += __shfl_down_sync(0xffffffffu, a2, off);
        a3 += __shfl_down_sync(0xffffffffu, a3, off);
    }
    if ((t & 31) == 0) {
        int w = t >> 5;
        red[w * 4 + 0] = a0; red[w * 4 + 1] = a1;
        red[w * 4 + 2] = a2; red[w * 4 + 3] = a3;
    }
    __syncthreads();
    if (t < ROWS_PER_BLK) {
        float total = g_ff[row0 + t];
#pragma unroll
        for (int w = 0; w < 8; w++) total += red[w * 4 + t];
        float ns = 0.8f * state[row0 + t] + 0.2f * total;
        out_state[row0 + t] = ns;
        float no = ns > 0.f ? tanhf(ns) : 0.f;    // retanh
        out_output[row0 + t] = no;
        no_sh[t] = no;
        __threadfence();                          // publish this thread's gmem writes
    }
    __syncthreads();

    // ---- per-batch software barrier: arrive, then spin (acquire) ----
    if (t == 0) {
        atomicAdd(&g_cnt[b], 1u);                 // arrive BEFORE wait -> no circular wait
        unsigned v;
        do {
            asm volatile("ld.global.acquire.gpu.u32 %0, [%1];" : "=r"(v) : "l"(g_cnt + b));
        } while (v < (unsigned)BLKS_PER_BATCH);
    }
    __syncthreads();

    // ---- pass 2: plasticity from register-held wh; gq chunked 2+2 to cap regs ----
    const float dab = 0.02f * da[b];
    const float c0 = dab * no_sh[0];
    const float c1 = dab * no_sh[1];
    const float c2 = dab * no_sh[2];
    const float c3 = dab * no_sh[3];

    float4 no = __ldcg((const float4*)(out_output + (b << 10) + 4 * t));  // cross-block -> bypass L1
    const unsigned* gqp = g_gq + i0 * HH + 4 * t;
    const size_t base = (size_t)row0 * HH + 4 * t;

    {
        uint4 gA = *(const uint4*)(gqp);
        uint4 gB = *(const uint4*)(gqp + HH);
        __stcs((float4*)(out_w + base),      plast4(w0, gA, no, c0));
        __stcs((float4*)(out_w + base + HH), plast4(w1, gB, no, c1));
    }
    {
        uint4 gC = *(const uint4*)(gqp + 2 * HH);
        uint4 gD = *(const uint4*)(gqp + 3 * HH);
        __stcs((float4*)(out_w + base + 2 * HH), plast4(w2, gC, no, c2));
        __stcs((float4*)(out_w + base + 3 * HH), plast4(w3, gD, no, c3));
    }
}

extern "C" void kernel_launch(void* const* d_in, const int* in_sizes, int n_in,
                              void* d_out, int out_size) {
    const float* x      = (const float*)d_in[0];   // [B,I]
    const float* state  = (const float*)d_in[1];   // [B,H]
    const float* outp   = (const float*)d_in[2];   // [B,H]
    const float* wh     = (const float*)d_in[3];   // [B,H,H]
    const float* da     = (const float*)d_in[4];   // [B]
    const float* aux    = (const float*)d_in[5];   // [B,A]
    const float* Wx     = (const float*)d_in[6];   // [H,I]
    const float* Waux   = (const float*)d_in[7];   // [H,A]
    const float* Wh     = (const float*)d_in[8];   // [H,H]
    const float* bh     = (const float*)d_in[9];   // [H]
    const float* kappa  = (const float*)d_in[10];  // [H,H]
    const float* mask   = (const float*)d_in[11];  // [H,H]

    float* out_state  = (float*)d_out;                 // [B,H]
    float* out_output = (float*)d_out + BH;            // [B,H]
    float* out_w      = (float*)d_out + 2 * BH;        // [B,H,H]

    prep_soff<<<BH / 8, 256>>>(x, outp, aux, Wx, Waux, bh, mask);
    prep_gq<<<(HH * HH / 4 + 255) / 256, 256>>>((const float4*)Wh, (const float4*)kappa);
    k_fused<<<BH / ROWS_PER_BLK, 256>>>(wh, state, da, out_state, out_output, out_w);
}

// round 10
// speedup vs baseline: 1.1488x; 1.1488x over previous
#include <cuda_runtime.h>
#include <cuda_bf16.h>
#include <cstdint>

#define BB 64
#define II 128
#define AA 16
#define HH 1024
#define BH (BB*HH)

// scratch (static __device__ — no allocations)
__device__ float g_sign[HH];            // column sign (+1 excitatory / -1 inhibitory)
__device__ unsigned int g_gq[HH*HH];    // packed bf16: lo = 0.02*|W_h|, hi = |kappa|

// ---------------- prep: pack (0.02*|W_h|, |kappa|) as bf16x2; extract sign ----------------
__global__ void prep_gq(const float4* __restrict__ Wh, const float4* __restrict__ kap,
                        const float* __restrict__ mask) {
    int idx = blockIdx.x * blockDim.x + threadIdx.x;    // over HH*HH/4
    if (idx < HH) {
        // mask_h[r, j] = sign_j for any r != j (zero diagonal) -> read row (j+1)%H
        g_sign[idx] = mask[((idx + 1) & (HH - 1)) * HH + idx];
    }
    if (idx >= HH * HH / 4) return;
    float4 wv = Wh[idx];
    float4 kv = kap[idx];
    uint4 o;
    o.x = (unsigned)__bfloat16_as_ushort(__float2bfloat16_rn(0.02f * fabsf(wv.x)))
        | ((unsigned)__bfloat16_as_ushort(__float2bfloat16_rn(fabsf(kv.x))) << 16);
    o.y = (unsigned)__bfloat16_as_ushort(__float2bfloat16_rn(0.02f * fabsf(wv.y)))
        | ((unsigned)__bfloat16_as_ushort(__float2bfloat16_rn(fabsf(kv.y))) << 16);
    o.z = (unsigned)__bfloat16_as_ushort(__float2bfloat16_rn(0.02f * fabsf(wv.z)))
        | ((unsigned)__bfloat16_as_ushort(__float2bfloat16_rn(fabsf(kv.z))) << 16);
    o.w = (unsigned)__bfloat16_as_ushort(__float2bfloat16_rn(0.02f * fabsf(wv.w)))
        | ((unsigned)__bfloat16_as_ushort(__float2bfloat16_rn(fabsf(kv.w))) << 16);
    ((uint4*)g_gq)[idx] = o;
}

// ---------------- pass 1: TMA bulk-load 4 wh rows to smem; ff computed in flight ----------------
__global__ __launch_bounds__(256) void k_state_tma(const float* __restrict__ wh,
                                                   const float* __restrict__ state,
                                                   const float* __restrict__ outp,
                                                   const float* __restrict__ x,
                                                   const float* __restrict__ aux,
                                                   const float* __restrict__ Wx,
                                                   const float* __restrict__ Waux,
                                                   const float* __restrict__ bh,
                                                   float* __restrict__ out_state,
                                                   float* __restrict__ out_output) {
    __shared__ alignas(16) float buf[4 * HH];     // 16 KB: 4 wh rows
    __shared__ float red[8 * 4];
    __shared__ float ff_sh[4];
    __shared__ alignas(8) unsigned long long mbar;

    const int row0 = blockIdx.x * 4;              // 4 consecutive rows, same batch
    const int b = row0 >> 10;
    const int i0 = row0 & (HH - 1);
    const int t = threadIdx.x;
    const int warp = t >> 5;
    const int lane = t & 31;

    // mbarrier init + bulk copy issue (single thread)
    unsigned mbar_a;
    asm("{ .reg .u64 tmp; cvta.to.shared.u64 tmp, %1; cvt.u32.u64 %0, tmp; }"
        : "=r"(mbar_a) : "l"(&mbar));
    unsigned buf_a;
    asm("{ .reg .u64 tmp; cvta.to.shared.u64 tmp, %1; cvt.u32.u64 %0, tmp; }"
        : "=r"(buf_a) : "l"(buf));
    if (t == 0) {
        asm volatile("mbarrier.init.shared.b64 [%0], 1;" :: "r"(mbar_a) : "memory");
    }
    __syncthreads();
    if (t == 0) {
        asm volatile("mbarrier.arrive.expect_tx.shared.b64 _, [%0], %1;"
                     :: "r"(mbar_a), "r"(4 * HH * 4) : "memory");
        asm volatile("cp.async.bulk.shared::cta.global.mbarrier::complete_tx::bytes "
                     "[%0], [%1], %2, [%3];"
                     :: "r"(buf_a), "l"(wh + (size_t)row0 * HH), "r"(4 * HH * 4), "r"(mbar_a)
                     : "memory");
    }

    // ---- while TMA is in flight: warps 0-3 compute ff for the 4 rows ----
    if (warp < 4) {
        int i = i0 + warp;
        float4 w = ((const float4*)(Wx + i * II))[lane];
        float4 xv = ((const float4*)(x + b * II))[lane];
        float acc = fmaxf(xv.x, 0.f) * fabsf(w.x) + fmaxf(xv.y, 0.f) * fabsf(w.y)
                  + fmaxf(xv.z, 0.f) * fabsf(w.z) + fmaxf(xv.w, 0.f) * fabsf(w.w);
        if (lane < 4) {
            float4 wa = ((const float4*)(Waux + i * AA))[lane];
            float4 av = ((const float4*)(aux + b * AA))[lane];
            acc += fmaxf(av.x, 0.f) * fabsf(wa.x) + fmaxf(av.y, 0.f) * fabsf(wa.y)
                 + fmaxf(av.z, 0.f) * fabsf(wa.z) + fmaxf(av.w, 0.f) * fabsf(wa.w);
        }
#pragma unroll
        for (int off = 16; off; off >>= 1) acc += __shfl_down_sync(0xffffffffu, acc, off);
        if (lane == 0) ff_sh[warp] = acc + bh[i];
    }

    // signed output vector slice for this thread (L2-hot)
    float4 sg = ((const float4*)g_sign)[t];
    float4 ov = ((const float4*)(outp + (b << 10)))[t];
    float4 s = make_float4(sg.x * ov.x, sg.y * ov.y, sg.z * ov.z, sg.w * ov.w);

    // ---- wait for wh tile ----
    asm volatile(
        "{\n\t"
        ".reg .pred P;\n\t"
        "W%=:\n\t"
        "mbarrier.try_wait.parity.acquire.cta.shared::cta.b64 P, [%0], 0, 0x989680;\n\t"
        "@P bra D%=;\n\t"
        "bra W%=;\n\t"
        "D%=:\n\t"
        "}" :: "r"(mbar_a) : "memory");

    // ---- dot products from smem ----
    float4 w0 = ((const float4*)buf)[t];
    float4 w1 = ((const float4*)buf)[t + 256];
    float4 w2 = ((const float4*)buf)[t + 512];
    float4 w3 = ((const float4*)buf)[t + 768];

    float a0 = w0.x * s.x + w0.y * s.y + w0.z * s.z + w0.w * s.w;
    float a1 = w1.x * s.x + w1.y * s.y + w1.z * s.z + w1.w * s.w;
    float a2 = w2.x * s.x + w2.y * s.y + w2.z * s.z + w2.w * s.w;
    float a3 = w3.x * s.x + w3.y * s.y + w3.z * s.z + w3.w * s.w;

    // zero-diagonal fixups
#pragma unroll
    for (int r = 0; r < 4; r++) {
        int i = i0 + r;
        if (t == (i >> 2)) {
            int c = i & 3;
            float4 w = (r == 0) ? w0 : (r == 1) ? w1 : (r == 2) ? w2 : w3;
            float wv = (c == 0) ? w.x : (c == 1) ? w.y : (c == 2) ? w.z : w.w;
            float sv = (c == 0) ? s.x : (c == 1) ? s.y : (c == 2) ? s.z : s.w;
            float d = wv * sv;
            if (r == 0) a0 -= d; else if (r == 1) a1 -= d; else if (r == 2) a2 -= d; else a3 -= d;
        }
    }
#pragma unroll
    for (int off = 16; off; off >>= 1) {
        a0 += __shfl_down_sync(0xffffffffu, a0, off);
        a1 += __shfl_down_sync(0xffffffffu, a1, off);
        a2 += __shfl_down_sync(0xffffffffu, a2, off);
        a3 += __shfl_down_sync(0xffffffffu, a3, off);
    }
    if (lane == 0) {
        red[warp * 4 + 0] = a0; red[warp * 4 + 1] = a1;
        red[warp * 4 + 2] = a2; red[warp * 4 + 3] = a3;
    }
    __syncthreads();
    if (t < 4) {
        float total = ff_sh[t];
#pragma unroll
        for (int w = 0; w < 8; w++) total += red[w * 4 + t];
        float ns = 0.8f * state[row0 + t] + 0.2f * total;
        out_state[row0 + t] = ns;
        out_output[row0 + t] = ns > 0.f ? tanhf(ns) : 0.f;   // retanh
    }
}

// ---------------- pass 2: plasticity (reverse row order to catch wh tail in L2) ----------------
__device__ __forceinline__ float4 plast4(float4 w, uint4 gq, float4 no, float coef) {
    float4 r;
    {
        float g = __bfloat162float(__ushort_as_bfloat16((unsigned short)(gq.x & 0xffff)));
        float q = __bfloat162float(__ushort_as_bfloat16((unsigned short)(gq.x >> 16)));
        r.x = fminf(fmaxf(g + 0.98f * w.x + coef * q * no.x, 0.f), 1.f);
    }
    {
        float g = __bfloat162float(__ushort_as_bfloat16((unsigned short)(gq.y & 0xffff)));
        float q = __bfloat162float(__ushort_as_bfloat16((unsigned short)(gq.y >> 16)));
        r.y = fminf(fmaxf(g + 0.98f * w.y + coef * q * no.y, 0.f), 1.f);
    }
    {
        float g = __bfloat162float(__ushort_as_bfloat16((unsigned short)(gq.z & 0xffff)));
        float q = __bfloat162float(__ushort_as_bfloat16((unsigned short)(gq.z >> 16)));
        r.z = fminf(fmaxf(g + 0.98f * w.z + coef * q * no.z, 0.f), 1.f);
    }
    {
        float g = __bfloat162float(__ushort_as_bfloat16((unsigned short)(gq.w & 0xffff)));
        float q = __bfloat162float(__ushort_as_bfloat16((unsigned short)(gq.w >> 16)));
        r.w = fminf(fmaxf(g + 0.98f * w.w + coef * q * no.w, 0.f), 1.f);
    }
    return r;
}

__global__ __launch_bounds__(128) void k_plast(const float* __restrict__ wh,
                                               const float* __restrict__ da,
                                               const float* __restrict__ newout,
                                               float* __restrict__ out_w) {
    const int row = (BH - 1) - blockIdx.x;        // reverse order: hit wh tail still in L2
    const int b = row >> 10;
    const int i = row & (HH - 1);
    const float no_i = newout[row];
    const float coef = 0.02f * da[b] * no_i;      // DT * da * new_output_i

    const int t = threadIdx.x;                    // 128 threads x 2 float4 chunks
    const size_t base = (size_t)row * HH;

    // front-batch both DRAM reads (independent -> MLP=2)
    float4 wA = __ldcs((const float4*)(wh + base + 4 * t));
    float4 wB = __ldcs((const float4*)(wh + base + 512 + 4 * t));
    uint4 gqA = *(const uint4*)(g_gq + i * HH + 4 * t);
    uint4 gqB = *(const uint4*)(g_gq + i * HH + 512 + 4 * t);
    float4 noA = *(const float4*)(newout + (b << 10) + 4 * t);
    float4 noB = *(const float4*)(newout + (b << 10) + 512 + 4 * t);

    __stcs((float4*)(out_w + base + 4 * t),       plast4(wA, gqA, noA, coef));
    __stcs((float4*)(out_w + base + 512 + 4 * t), plast4(wB, gqB, noB, coef));
}

extern "C" void kernel_launch(void* const* d_in, const int* in_sizes, int n_in,
                              void* d_out, int out_size) {
    const float* x      = (const float*)d_in[0];   // [B,I]
    const float* state  = (const float*)d_in[1];   // [B,H]
    const float* outp   = (const float*)d_in[2];   // [B,H]
    const float* wh     = (const float*)d_in[3];   // [B,H,H]
    const float* da     = (const float*)d_in[4];   // [B]
    const float* aux    = (const float*)d_in[5];   // [B,A]
    const float* Wx     = (const float*)d_in[6];   // [H,I]
    const float* Waux   = (const float*)d_in[7];   // [H,A]
    const float* Wh     = (const float*)d_in[8];   // [H,H]
    const float* bh     = (const float*)d_in[9];   // [H]
    const float* kappa  = (const float*)d_in[10];  // [H,H]
    const float* mask   = (const float*)d_in[11];  // [H,H]

    float* out_state  = (float*)d_out;                 // [B,H]
    float* out_output = (float*)d_out + BH;            // [B,H]
    float* out_w      = (float*)d_out + 2 * BH;        // [B,H,H]

    prep_gq<<<(HH * HH / 4 + 255) / 256, 256>>>((const float4*)Wh, (const float4*)kappa, mask);
    k_state_tma<<<BH / 4, 256>>>(wh, state, outp, x, aux, Wx, Waux, bh, out_state, out_output);
    k_plast<<<BH, 128>>>(wh, da, out_output, out_w);
}

// round 11
// speedup vs baseline: 1.2834x; 1.1171x over previous
#include <cuda_runtime.h>
#include <cuda_bf16.h>
#include <cstdint>

#define BB 64
#define II 128
#define AA 16
#define HH 1024
#define BH (BB*HH)
#define LAG 3                       // plast chases state by 3 batches (24MB << L2)
#define NSLOT (BB + LAG)

// scratch (static __device__ — no allocations)
__device__ float g_sign[HH];            // column sign (+1 excitatory / -1 inhibitory)
__device__ unsigned int g_gq[HH*HH];    // packed bf16: lo = 0.02*|W_h|, hi = |kappa|
__device__ unsigned int g_cnt[BB];      // per-batch state-block completion counters

// ---------------- prep: pack (0.02*|W_h|, |kappa|) as bf16x2; sign; reset counters ----------------
__global__ void prep_gq(const float4* __restrict__ Wh, const float4* __restrict__ kap,
                        const float* __restrict__ mask) {
    int idx = blockIdx.x * blockDim.x + threadIdx.x;    // over HH*HH/4
    if (idx < BB) g_cnt[idx] = 0u;                      // reset barrier state every call
    if (idx < HH) {
        // mask_h[r, j] = sign_j for any r != j (zero diagonal) -> read row (j+1)%H
        g_sign[idx] = mask[((idx + 1) & (HH - 1)) * HH + idx];
    }
    if (idx >= HH * HH / 4) return;
    float4 wv = Wh[idx];
    float4 kv = kap[idx];
    uint4 o;
    o.x = (unsigned)__bfloat16_as_ushort(__float2bfloat16_rn(0.02f * fabsf(wv.x)))
        | ((unsigned)__bfloat16_as_ushort(__float2bfloat16_rn(fabsf(kv.x))) << 16);
    o.y = (unsigned)__bfloat16_as_ushort(__float2bfloat16_rn(0.02f * fabsf(wv.y)))
        | ((unsigned)__bfloat16_as_ushort(__float2bfloat16_rn(fabsf(kv.y))) << 16);
    o.z = (unsigned)__bfloat16_as_ushort(__float2bfloat16_rn(0.02f * fabsf(wv.z)))
        | ((unsigned)__bfloat16_as_ushort(__float2bfloat16_rn(fabsf(kv.z))) << 16);
    o.w = (unsigned)__bfloat16_as_ushort(__float2bfloat16_rn(0.02f * fabsf(wv.w)))
        | ((unsigned)__bfloat16_as_ushort(__float2bfloat16_rn(fabsf(kv.w))) << 16);
    ((uint4*)g_gq)[idx] = o;
}

// ---------------- pass-2 math on one float4 column chunk ----------------
__device__ __forceinline__ float4 plast4(float4 w, uint4 gq, float4 no, float coef) {
    float4 r;
    {
        float g = __bfloat162float(__ushort_as_bfloat16((unsigned short)(gq.x & 0xffff)));
        float q = __bfloat162float(__ushort_as_bfloat16((unsigned short)(gq.x >> 16)));
        r.x = fminf(fmaxf(g + 0.98f * w.x + coef * q * no.x, 0.f), 1.f);
    }
    {
        float g = __bfloat162float(__ushort_as_bfloat16((unsigned short)(gq.y & 0xffff)));
        float q = __bfloat162float(__ushort_as_bfloat16((unsigned short)(gq.y >> 16)));
        r.y = fminf(fmaxf(g + 0.98f * w.y + coef * q * no.y, 0.f), 1.f);
    }
    {
        float g = __bfloat162float(__ushort_as_bfloat16((unsigned short)(gq.z & 0xffff)));
        float q = __bfloat162float(__ushort_as_bfloat16((unsigned short)(gq.z >> 16)));
        r.z = fminf(fmaxf(g + 0.98f * w.z + coef * q * no.z, 0.f), 1.f);
    }
    {
        float g = __bfloat162float(__ushort_as_bfloat16((unsigned short)(gq.w & 0xffff)));
        float q = __bfloat162float(__ushort_as_bfloat16((unsigned short)(gq.w >> 16)));
        r.w = fminf(fmaxf(g + 0.98f * w.w + coef * q * no.w, 0.f), 1.f);
    }
    return r;
}

// ---------------- mega kernel: state blocks + chasing plast blocks, one launch ----------------
__global__ __launch_bounds__(256) void k_mega(const float* __restrict__ wh,
                                              const float* __restrict__ state,
                                              const float* __restrict__ outp,
                                              const float* __restrict__ x,
                                              const float* __restrict__ aux,
                                              const float* __restrict__ Wx,
                                              const float* __restrict__ Waux,
                                              const float* __restrict__ bh,
                                              const float* __restrict__ da,
                                              float* __restrict__ out_state,
                                              float* __restrict__ out_output,
                                              float* __restrict__ out_w) {
    const int slot = blockIdx.x >> 9;             // 512 blocks per slot
    const int sub  = blockIdx.x & 511;
    const int t = threadIdx.x;

    if (sub < 256) {
        // ================= STATE path: batch = slot =================
        if (slot >= BB) return;
        const int b = slot;
        const int row0 = (b << 10) + sub * 4;     // 4 consecutive rows
        const int i0 = sub * 4;
        const int warp = t >> 5;
        const int lane = t & 31;
        __shared__ float red[8 * 4];
        __shared__ float ff_sh[4];

        // front-batched wh loads (fills L2 for the chasing plast blocks)
        const float4* wp = (const float4*)(wh + (size_t)row0 * HH) + t;
        float4 w0 = wp[0];
        float4 w1 = wp[256];
        float4 w2 = wp[512];
        float4 w3 = wp[768];

        // signed output slice (L2-hot small vectors)
        float4 sg = ((const float4*)g_sign)[t];
        float4 ov = ((const float4*)(outp + (b << 10)))[t];
        float4 s = make_float4(sg.x * ov.x, sg.y * ov.y, sg.z * ov.z, sg.w * ov.w);

        // ff for the 4 rows, computed by warps 0-3 while wh loads are in flight
        if (warp < 4) {
            int i = i0 + warp;
            float4 w = ((const float4*)(Wx + i * II))[lane];
            float4 xv = ((const float4*)(x + b * II))[lane];
            float acc = fmaxf(xv.x, 0.f) * fabsf(w.x) + fmaxf(xv.y, 0.f) * fabsf(w.y)
                      + fmaxf(xv.z, 0.f) * fabsf(w.z) + fmaxf(xv.w, 0.f) * fabsf(w.w);
            if (lane < 4) {
                float4 wa = ((const float4*)(Waux + i * AA))[lane];
                float4 av = ((const float4*)(aux + b * AA))[lane];
                acc += fmaxf(av.x, 0.f) * fabsf(wa.x) + fmaxf(av.y, 0.f) * fabsf(wa.y)
                     + fmaxf(av.z, 0.f) * fabsf(wa.z) + fmaxf(av.w, 0.f) * fabsf(wa.w);
            }
#pragma unroll
            for (int off = 16; off; off >>= 1) acc += __shfl_down_sync(0xffffffffu, acc, off);
            if (lane == 0) ff_sh[warp] = acc + bh[i];
        }

        float a0 = w0.x * s.x + w0.y * s.y + w0.z * s.z + w0.w * s.w;
        float a1 = w1.x * s.x + w1.y * s.y + w1.z * s.z + w1.w * s.w;
        float a2 = w2.x * s.x + w2.y * s.y + w2.z * s.z + w2.w * s.w;
        float a3 = w3.x * s.x + w3.y * s.y + w3.z * s.z + w3.w * s.w;

        // zero-diagonal fixups
#pragma unroll
        for (int r = 0; r < 4; r++) {
            int i = i0 + r;
            if (t == (i >> 2)) {
                int c = i & 3;
                float4 w = (r == 0) ? w0 : (r == 1) ? w1 : (r == 2) ? w2 : w3;
                float wv = (c == 0) ? w.x : (c == 1) ? w.y : (c == 2) ? w.z : w.w;
                float sv = (c == 0) ? s.x : (c == 1) ? s.y : (c == 2) ? s.z : s.w;
                float d = wv * sv;
                if (r == 0) a0 -= d; else if (r == 1) a1 -= d; else if (r == 2) a2 -= d; else a3 -= d;
            }
        }
#pragma unroll
        for (int off = 16; off; off >>= 1) {
            a0 += __shfl_down_sync(0xffffffffu, a0, off);
            a1 += __shfl_down_sync(0xffffffffu, a1, off);
            a2 += __shfl_down_sync(0xffffffffu, a2, off);
            a3 += __shfl_down_sync(0xffffffffu, a3, off);
        }
        if (lane == 0) {
            red[warp * 4 + 0] = a0; red[warp * 4 + 1] = a1;
            red[warp * 4 + 2] = a2; red[warp * 4 + 3] = a3;
        }
        __syncthreads();
        if (t < 4) {
            float total = ff_sh[t];
#pragma unroll
            for (int w = 0; w < 8; w++) total += red[w * 4 + t];
            float ns = 0.8f * state[row0 + t] + 0.2f * total;
            out_state[row0 + t] = ns;
            out_output[row0 + t] = ns > 0.f ? tanhf(ns) : 0.f;   // retanh
            __threadfence();                       // publish before arrive
        }
        __syncthreads();
        if (t == 0) atomicAdd(&g_cnt[b], 1u);      // signal: this block's 4 rows done
    } else {
        // ================= PLAST path: batch = slot - LAG =================
        const int b = slot - LAG;
        if (b < 0 || b >= BB) return;
        const int row0 = (b << 10) + (sub - 256) * 4;
        const int i0 = row0 & (HH - 1);

        // wait until all 256 state blocks of batch b arrived
        if (t == 0) {
            unsigned v;
            do {
                asm volatile("ld.global.acquire.gpu.u32 %0, [%1];" : "=r"(v) : "l"(g_cnt + b));
                if (v < 256u) __nanosleep(200);
            } while (v < 256u);
        }
        __syncthreads();

        const float dab = 0.02f * da[b];
        const float c0 = dab * __ldcg(out_output + row0);
        const float c1 = dab * __ldcg(out_output + row0 + 1);
        const float c2 = dab * __ldcg(out_output + row0 + 2);
        const float c3 = dab * __ldcg(out_output + row0 + 3);

        float4 no = __ldcg((const float4*)(out_output + (b << 10) + 4 * t));  // bypass L1
        const unsigned* gqp = g_gq + i0 * HH + 4 * t;
        const size_t base = (size_t)row0 * HH + 4 * t;

        // wh reads: L2 hits (state(b) pulled them 3 slots ago); evict-first after use
        float4 wA = __ldcs((const float4*)(wh + base));
        float4 wB = __ldcs((const float4*)(wh + base + HH));
        {
            uint4 gA = *(const uint4*)(gqp);
            uint4 gB = *(const uint4*)(gqp + HH);
            __stcs((float4*)(out_w + base),      plast4(wA, gA, no, c0));
            __stcs((float4*)(out_w + base + HH), plast4(wB, gB, no, c1));
        }
        float4 wC = __ldcs((const float4*)(wh + base + 2 * HH));
        float4 wD = __ldcs((const float4*)(wh + base + 3 * HH));
        {
            uint4 gC = *(const uint4*)(gqp + 2 * HH);
            uint4 gD = *(const uint4*)(gqp + 3 * HH);
            __stcs((float4*)(out_w + base + 2 * HH), plast4(wC, gC, no, c2));
            __stcs((float4*)(out_w + base + 3 * HH), plast4(wD, gD, no, c3));
        }
    }
}

extern "C" void kernel_launch(void* const* d_in, const int* in_sizes, int n_in,
                              void* d_out, int out_size) {
    const float* x      = (const float*)d_in[0];   // [B,I]
    const float* state  = (const float*)d_in[1];   // [B,H]
    const float* outp   = (const float*)d_in[2];   // [B,H]
    const float* wh     = (const float*)d_in[3];   // [B,H,H]
    const float* da     = (const float*)d_in[4];   // [B]
    const float* aux    = (const float*)d_in[5];   // [B,A]
    const float* Wx     = (const float*)d_in[6];   // [H,I]
    const float* Waux   = (const float*)d_in[7];   // [H,A]
    const float* Wh     = (const float*)d_in[8];   // [H,H]
    const float* bh     = (const float*)d_in[9];   // [H]
    const float* kappa  = (const float*)d_in[10];  // [H,H]
    const float* mask   = (const float*)d_in[11];  // [H,H]

    float* out_state  = (float*)d_out;                 // [B,H]
    float* out_output = (float*)d_out + BH;            // [B,H]
    float* out_w      = (float*)d_out + 2 * BH;        // [B,H,H]

    prep_gq<<<(HH * HH / 4 + 255) / 256, 256>>>((const float4*)Wh, (const float4*)kappa, mask);
    k_mega<<<NSLOT * 512, 256>>>(wh, state, outp, x, aux, Wx, Waux, bh, da,
                                 out_state, out_output, out_w);
}

// round 12
// speedup vs baseline: 1.3076x; 1.0189x over previous
#include <cuda_runtime.h>
#include <cuda_bf16.h>
#include <cstdint>

#define BB 64
#define II 128
#define AA 16
#define HH 1024
#define BH (BB*HH)
#define LAG 3                       // plast chases state by 3 batches (~50MB window << L2)
#define NSLOT (BB + LAG)

// scratch (static __device__ — no allocations)
__device__ float g_sign[HH];            // column sign (+1 excitatory / -1 inhibitory)
__device__ unsigned int g_gq[HH*HH];    // packed bf16: lo = 0.02*|W_h|, hi = |kappa|
__device__ unsigned int g_cnt[BB];      // per-batch state completion counters

// ---------------- prep: pack (0.02*|W_h|, |kappa|) as bf16x2; sign; reset counters ----------------
__global__ void prep_gq(const float4* __restrict__ Wh, const float4* __restrict__ kap,
                        const float* __restrict__ mask) {
    int idx = blockIdx.x * blockDim.x + threadIdx.x;    // over HH*HH/4
    if (idx < BB) g_cnt[idx] = 0u;                      // reset barrier state every call
    if (idx < HH) {
        // mask_h[r, j] = sign_j for any r != j (zero diagonal) -> read row (j+1)%H
        g_sign[idx] = mask[((idx + 1) & (HH - 1)) * HH + idx];
    }
    if (idx >= HH * HH / 4) return;
    float4 wv = Wh[idx];
    float4 kv = kap[idx];
    uint4 o;
    o.x = (unsigned)__bfloat16_as_ushort(__float2bfloat16_rn(0.02f * fabsf(wv.x)))
        | ((unsigned)__bfloat16_as_ushort(__float2bfloat16_rn(fabsf(kv.x))) << 16);
    o.y = (unsigned)__bfloat16_as_ushort(__float2bfloat16_rn(0.02f * fabsf(wv.y)))
        | ((unsigned)__bfloat16_as_ushort(__float2bfloat16_rn(fabsf(kv.y))) << 16);
    o.z = (unsigned)__bfloat16_as_ushort(__float2bfloat16_rn(0.02f * fabsf(wv.z)))
        | ((unsigned)__bfloat16_as_ushort(__float2bfloat16_rn(fabsf(kv.z))) << 16);
    o.w = (unsigned)__bfloat16_as_ushort(__float2bfloat16_rn(0.02f * fabsf(wv.w)))
        | ((unsigned)__bfloat16_as_ushort(__float2bfloat16_rn(fabsf(kv.w))) << 16);
    ((uint4*)g_gq)[idx] = o;
}

// ---------------- pass-2 math on one float4 column chunk ----------------
__device__ __forceinline__ float4 plast4(float4 w, uint4 gq, float4 no, float coef) {
    float4 r;
    {
        float g = __bfloat162float(__ushort_as_bfloat16((unsigned short)(gq.x & 0xffff)));
        float q = __bfloat162float(__ushort_as_bfloat16((unsigned short)(gq.x >> 16)));
        r.x = fminf(fmaxf(g + 0.98f * w.x + coef * q * no.x, 0.f), 1.f);
    }
    {
        float g = __bfloat162float(__ushort_as_bfloat16((unsigned short)(gq.y & 0xffff)));
        float q = __bfloat162float(__ushort_as_bfloat16((unsigned short)(gq.y >> 16)));
        r.y = fminf(fmaxf(g + 0.98f * w.y + coef * q * no.y, 0.f), 1.f);
    }
    {
        float g = __bfloat162float(__ushort_as_bfloat16((unsigned short)(gq.z & 0xffff)));
        float q = __bfloat162float(__ushort_as_bfloat16((unsigned short)(gq.z >> 16)));
        r.z = fminf(fmaxf(g + 0.98f * w.z + coef * q * no.z, 0.f), 1.f);
    }
    {
        float g = __bfloat162float(__ushort_as_bfloat16((unsigned short)(gq.w & 0xffff)));
        float q = __bfloat162float(__ushort_as_bfloat16((unsigned short)(gq.w >> 16)));
        r.w = fminf(fmaxf(g + 0.98f * w.w + coef * q * no.w, 0.f), 1.f);
    }
    return r;
}

// ---------------- mega kernel: state(slot) then plast(slot-LAG), same block ----------------
__global__ __launch_bounds__(256) void k_mega(const float* __restrict__ wh,
                                              const float* __restrict__ state,
                                              const float* __restrict__ outp,
                                              const float* __restrict__ x,
                                              const float* __restrict__ aux,
                                              const float* __restrict__ Wx,
                                              const float* __restrict__ Waux,
                                              const float* __restrict__ bh,
                                              const float* __restrict__ da,
                                              float* __restrict__ out_state,
                                              float* __restrict__ out_output,
                                              float* __restrict__ out_w) {
    const int slot = blockIdx.x >> 8;             // 256 blocks per slot
    const int sub  = blockIdx.x & 255;
    const int t = threadIdx.x;
    const int warp = t >> 5;
    const int lane = t & 31;
    const int i0 = sub * 4;                       // rows i0..i0+3 (same for both phases)
    __shared__ float red[8 * 4];
    __shared__ float ff_sh[4];

    // ================= phase 1: STATE for batch = slot =================
    if (slot < BB) {
        const int b = slot;
        const int row0 = (b << 10) + i0;

        // front-batched wh loads (MLP=4; also fills L2 for the chasing plast phase)
        const float4* wp = (const float4*)(wh + (size_t)row0 * HH) + t;
        float4 w0 = wp[0];
        float4 w1 = wp[256];
        float4 w2 = wp[512];
        float4 w3 = wp[768];

        // signed output slice (L2-hot small vectors)
        float4 sg = ((const float4*)g_sign)[t];
        float4 ov = ((const float4*)(outp + (b << 10)))[t];
        float4 s = make_float4(sg.x * ov.x, sg.y * ov.y, sg.z * ov.z, sg.w * ov.w);

        // ff for the 4 rows, computed by warps 0-3 while wh loads are in flight
        if (warp < 4) {
            int i = i0 + warp;
            float4 w = ((const float4*)(Wx + i * II))[lane];
            float4 xv = ((const float4*)(x + b * II))[lane];
            float acc = fmaxf(xv.x, 0.f) * fabsf(w.x) + fmaxf(xv.y, 0.f) * fabsf(w.y)
                      + fmaxf(xv.z, 0.f) * fabsf(w.z) + fmaxf(xv.w, 0.f) * fabsf(w.w);
            if (lane < 4) {
                float4 wa = ((const float4*)(Waux + i * AA))[lane];
                float4 av = ((const float4*)(aux + b * AA))[lane];
                acc += fmaxf(av.x, 0.f) * fabsf(wa.x) + fmaxf(av.y, 0.f) * fabsf(wa.y)
                     + fmaxf(av.z, 0.f) * fabsf(wa.z) + fmaxf(av.w, 0.f) * fabsf(wa.w);
            }
#pragma unroll
            for (int off = 16; off; off >>= 1) acc += __shfl_down_sync(0xffffffffu, acc, off);
            if (lane == 0) ff_sh[warp] = acc + bh[i];
        }

        float a0 = w0.x * s.x + w0.y * s.y + w0.z * s.z + w0.w * s.w;
        float a1 = w1.x * s.x + w1.y * s.y + w1.z * s.z + w1.w * s.w;
        float a2 = w2.x * s.x + w2.y * s.y + w2.z * s.z + w2.w * s.w;
        float a3 = w3.x * s.x + w3.y * s.y + w3.z * s.z + w3.w * s.w;

        // zero-diagonal fixups
#pragma unroll
        for (int r = 0; r < 4; r++) {
            int i = i0 + r;
            if (t == (i >> 2)) {
                int c = i & 3;
                float4 w = (r == 0) ? w0 : (r == 1) ? w1 : (r == 2) ? w2 : w3;
                float wv = (c == 0) ? w.x : (c == 1) ? w.y : (c == 2) ? w.z : w.w;
                float sv = (c == 0) ? s.x : (c == 1) ? s.y : (c == 2) ? s.z : s.w;
                float d = wv * sv;
                if (r == 0) a0 -= d; else if (r == 1) a1 -= d; else if (r == 2) a2 -= d; else a3 -= d;
            }
        }
#pragma unroll
        for (int off = 16; off; off >>= 1) {
            a0 += __shfl_down_sync(0xffffffffu, a0, off);
            a1 += __shfl_down_sync(0xffffffffu, a1, off);
            a2 += __shfl_down_sync(0xffffffffu, a2, off);
            a3 += __shfl_down_sync(0xffffffffu, a3, off);
        }
        if (lane == 0) {
            red[warp * 4 + 0] = a0; red[warp * 4 + 1] = a1;
            red[warp * 4 + 2] = a2; red[warp * 4 + 3] = a3;
        }
        __syncthreads();
        if (t < 4) {
            float total = ff_sh[t];
#pragma unroll
            for (int w = 0; w < 8; w++) total += red[w * 4 + t];
            float ns = 0.8f * state[row0 + t] + 0.2f * total;
            out_state[row0 + t] = ns;
            out_output[row0 + t] = ns > 0.f ? tanhf(ns) : 0.f;   // retanh
            __threadfence();                       // publish before arrive
        }
        __syncthreads();
        if (t == 0) atomicAdd(&g_cnt[b], 1u);      // signal: this block's 4 rows done
    }

    // ================= phase 2: PLAST for batch = slot - LAG =================
    {
        const int b = slot - LAG;
        if (b < 0 || b >= BB) return;
        const int row0 = (b << 10) + i0;

        // wait until all 256 state blocks of batch b arrived (normally already true)
        if (t == 0) {
            unsigned v;
            do {
                asm volatile("ld.global.acquire.gpu.u32 %0, [%1];" : "=r"(v) : "l"(g_cnt + b));
                if (v < 256u) __nanosleep(100);
            } while (v < 256u);
        }
        __syncthreads();

        const float dab = 0.02f * da[b];
        const float c0 = dab * __ldcg(out_output + row0);
        const float c1 = dab * __ldcg(out_output + row0 + 1);
        const float c2 = dab * __ldcg(out_output + row0 + 2);
        const float c3 = dab * __ldcg(out_output + row0 + 3);

        float4 no = __ldcg((const float4*)(out_output + (b << 10) + 4 * t));  // bypass L1
        const unsigned* gqp = g_gq + i0 * HH + 4 * t;
        const size_t base = (size_t)row0 * HH + 4 * t;

        // wh reads: L2 hits (state(b) pulled them LAG slots ago); evict-first after use
        float4 wA = __ldcs((const float4*)(wh + base));
        float4 wB = __ldcs((const float4*)(wh + base + HH));
        float4 wC = __ldcs((const float4*)(wh + base + 2 * HH));
        float4 wD = __ldcs((const float4*)(wh + base + 3 * HH));
        {
            uint4 gA = *(const uint4*)(gqp);
            uint4 gB = *(const uint4*)(gqp + HH);
            __stcs((float4*)(out_w + base),      plast4(wA, gA, no, c0));
            __stcs((float4*)(out_w + base + HH), plast4(wB, gB, no, c1));
        }
        {
            uint4 gC = *(const uint4*)(gqp + 2 * HH);
            uint4 gD = *(const uint4*)(gqp + 3 * HH);
            __stcs((float4*)(out_w + base + 2 * HH), plast4(wC, gC, no, c2));
            __stcs((float4*)(out_w + base + 3 * HH), plast4(wD, gD, no, c3));
        }
    }
}

extern "C" void kernel_launch(void* const* d_in, const int* in_sizes, int n_in,
                              void* d_out, int out_size) {
    const float* x      = (const float*)d_in[0];   // [B,I]
    const float* state  = (const float*)d_in[1];   // [B,H]
    const float* outp   = (const float*)d_in[2];   // [B,H]
    const float* wh     = (const float*)d_in[3];   // [B,H,H]
    const float* da     = (const float*)d_in[4];   // [B]
    const float* aux    = (const float*)d_in[5];   // [B,A]
    const float* Wx     = (const float*)d_in[6];   // [H,I]
    const float* Waux   = (const float*)d_in[7];   // [H,A]
    const float* Wh     = (const float*)d_in[8];   // [H,H]
    const float* bh     = (const float*)d_in[9];   // [H]
    const float* kappa  = (const float*)d_in[10];  // [H,H]
    const float* mask   = (const float*)d_in[11];  // [H,H]

    float* out_state  = (float*)d_out;                 // [B,H]
    float* out_output = (float*)d_out + BH;            // [B,H]
    float* out_w      = (float*)d_out + 2 * BH;        // [B,H,H]

    prep_gq<<<(HH * HH / 4 + 255) / 256, 256>>>((const float4*)Wh, (const float4*)kappa, mask);
    k_mega<<<NSLOT * 256, 256>>>(wh, state, outp, x, aux, Wx, Waux, bh, da,
                                 out_state, out_output, out_w);
}